// round 13
// baseline (speedup 1.0000x reference)
#include <cuda_runtime.h>
#include <cuda_bf16.h>
#include <math.h>
#include <stdint.h>

#define L_SEQ 16384
#define H_DIM 128
#define P_DIM 256
#define NSEQ  512          // 256 channels x {re, im}
#define NCHUNK 1024
#define CLEN   16          // NCHUNK * CLEN == L_SEQ

// ---------------------------------------------------------------------------
// Scratch (device globals)
__device__ float    g_buall[L_SEQ * NSEQ];        // fp32 Bu
__device__ uint32_t g_inH[L_SEQ * (H_DIM / 2)];   // input hi bf16-pairs, permuted
__device__ uint32_t g_inL[L_SEQ * (H_DIM / 2)];
__device__ uint32_t g_W1H[NSEQ * (H_DIM / 2)];    // [Br;Bi]
__device__ uint32_t g_W1L[NSEQ * (H_DIM / 2)];
__device__ uint32_t g_W2H[H_DIM * (NSEQ / 2)];    // [Cr,-Ci]
__device__ uint32_t g_W2L[H_DIM * (NSEQ / 2)];
__device__ float2   g_final[NSEQ * NCHUNK];       // [seq][chunk]
__device__ float2   g_initv[NCHUNK * NSEQ];       // [chunk][seq]

// ---------------------------------------------------------------------------
__device__ __forceinline__ uint32_t packbf(float lo, float hi) {  // lo -> bits[15:0]
    uint32_t r;
    asm("cvt.rn.bf16x2.f32 %0, %1, %2;" : "=r"(r) : "f"(hi), "f"(lo));
    return r;
}
__device__ __forceinline__ int pair_pos(int P) {  // permute pairs within 16-pair groups
    int pi = P & 15;
    return (P & ~15) | (((pi & 3) << 2) | (pi >> 2));
}
__device__ __forceinline__ float bfhi(float v) {
    return __bfloat162float(__float2bfloat16_rn(v));
}
__device__ __forceinline__ void mma_bf16(float* d, uint32_t a0, uint32_t a1,
                                         uint32_t a2, uint32_t a3,
                                         uint32_t b0, uint32_t b1) {
    asm volatile(
        "mma.sync.aligned.m16n8k16.row.col.f32.bf16.bf16.f32 "
        "{%0,%1,%2,%3},{%4,%5,%6,%7},{%8,%9},{%0,%1,%2,%3};\n"
        : "+f"(d[0]), "+f"(d[1]), "+f"(d[2]), "+f"(d[3])
        : "r"(a0), "r"(a1), "r"(a2), "r"(a3), "r"(b0), "r"(b1));
}
#define CP16(dst_u32, src_ptr) \
    asm volatile("cp.async.cg.shared.global [%0], [%1], 16;\n" :: "r"(dst_u32), "l"(src_ptr))

// ---------------------------------------------------------------------------
// Merged prep: input split + both weight packs.
__global__ void prep_all(const float* __restrict__ in, const float* __restrict__ B,
                         const float* __restrict__ C) {
    int i = blockIdx.x * blockDim.x + threadIdx.x;   // 0 .. L*64-1
    {   // input
        int row = i >> 6, P = i & 63;
        float v0 = in[row * 128 + 2 * P];
        float v1 = in[row * 128 + 2 * P + 1];
        float h0 = bfhi(v0), h1 = bfhi(v1);
        int col = pair_pos(P);
        g_inH[row * 64 + col] = packbf(h0, h1);
        g_inL[row * 64 + col] = packbf(v0 - h0, v1 - h1);
    }
    if (i < NSEQ * 64) {   // W1: rows 0..511, 64 pairs
        int row = i >> 6, P = i & 63;
        float v0, v1;
        if (row < P_DIM) {
            v0 = B[(row * H_DIM + 2 * P) * 2 + 0];
            v1 = B[(row * H_DIM + 2 * P + 1) * 2 + 0];
        } else {
            int r = row - P_DIM;
            v0 = B[(r * H_DIM + 2 * P) * 2 + 1];
            v1 = B[(r * H_DIM + 2 * P + 1) * 2 + 1];
        }
        float h0 = bfhi(v0), h1 = bfhi(v1);
        int col = pair_pos(P);
        g_W1H[row * 64 + col] = packbf(h0, h1);
        g_W1L[row * 64 + col] = packbf(v0 - h0, v1 - h1);
    }
    if (i < H_DIM * 256) {  // W2: rows 0..127, 256 pairs
        int row = i >> 8, P = i & 255;
        int k0 = 2 * P;
        float v0, v1;
        if (k0 < P_DIM) {
            v0 =  C[(row * P_DIM + k0) * 2 + 0];
            v1 =  C[(row * P_DIM + k0 + 1) * 2 + 0];
        } else {
            v0 = -C[(row * P_DIM + k0 - P_DIM) * 2 + 1];
            v1 = -C[(row * P_DIM + k0 + 1 - P_DIM) * 2 + 1];
        }
        float h0 = bfhi(v0), h1 = bfhi(v1);
        int col = pair_pos(P);
        g_W2H[row * 256 + col] = packbf(h0, h1);
        g_W2L[row * 256 + col] = packbf(v0 - h0, v1 - h1);
    }
}

// ---------------------------------------------------------------------------
__device__ __forceinline__ void get_consts(const float* __restrict__ A_diag,
                                           const float* __restrict__ steps, int p,
                                           float& m11, float& m12, float& m21, float& m22,
                                           float& c1, float& c2) {
    float A  = fmaxf(A_diag[p], 0.0f);
    float dt = 1.0f / (1.0f + __expf(-steps[p]));
    float schur = 1.0f / (1.0f + dt * dt * A);
    m11 = 1.0f - dt * dt * A * schur;
    m12 = -dt * A * schur;
    m21 = dt * schur;
    m22 = schur;
    c1 = m11 * dt;
    c2 = m21 * dt;
}

// ---------------------------------------------------------------------------
// GEMM1: 3xBF16 NT. BM=64, BN=64, BK=32, 128 threads (4 warps 2x2, warp tile
// 32x32). smem/stage 16KB, 2 stages. Fused passA epilogue (4 chunks of 16).
#define OFF_AL 1024
#define OFF_BH 2048
#define OFF_BL 3072
#define STAGE_U 4096
#define SBU_STR 65

__global__ void __launch_bounds__(128)
gemm1_fused(const uint32_t* __restrict__ AH_g, const uint32_t* __restrict__ AL_g,
            const uint32_t* __restrict__ BH_g, const uint32_t* __restrict__ BL_g,
            float* __restrict__ out,
            const float* __restrict__ A_diag, const float* __restrict__ steps) {
    extern __shared__ uint32_t smem_u[];
    const int N = NSEQ, K = H_DIM;
    const int tid  = threadIdx.x;
    const int lane = tid & 31;
    const int wid  = tid >> 5;
    const int warp_m = (wid & 1) * 32;
    const int warp_n = (wid >> 1) * 32;
    const int gr = lane >> 2;
    const int kq = lane & 3;
    const int bm = blockIdx.y * 64, bn = blockIdx.x * 64;
    const int KW = K >> 1;

    float acc[2][4][4];
    #pragma unroll
    for (int i = 0; i < 2; i++)
        #pragma unroll
        for (int j = 0; j < 4; j++)
            #pragma unroll
            for (int q = 0; q < 4; q++) acc[i][j][q] = 0.0f;

    const int nk = K >> 5;

    auto stage_load = [&](int kt, int s) {
        uint32_t* base = smem_u + s * STAGE_U;
        int kofs = kt << 4;
        #pragma unroll
        for (int it = 0; it < 2; it++) {
            int id = tid + it * 128;
            int r = id >> 2, c4 = (id & 3) << 2;
            CP16((uint32_t)__cvta_generic_to_shared(base + r * 16 + c4),
                 AH_g + (size_t)(bm + r) * KW + kofs + c4);
            CP16((uint32_t)__cvta_generic_to_shared(base + OFF_AL + r * 16 + c4),
                 AL_g + (size_t)(bm + r) * KW + kofs + c4);
            CP16((uint32_t)__cvta_generic_to_shared(base + OFF_BH + r * 16 + c4),
                 BH_g + (size_t)(bn + r) * KW + kofs + c4);
            CP16((uint32_t)__cvta_generic_to_shared(base + OFF_BL + r * 16 + c4),
                 BL_g + (size_t)(bn + r) * KW + kofs + c4);
        }
    };

    stage_load(0, 0);
    asm volatile("cp.async.commit_group;\n");

    for (int kt = 0; kt < nk; kt++) {
        int s = kt & 1;
        if (kt + 1 < nk) stage_load(kt + 1, s ^ 1);
        asm volatile("cp.async.commit_group;\n");
        asm volatile("cp.async.wait_group 1;\n");
        __syncthreads();

        uint32_t* base = smem_u + s * STAGE_U;
        uint4 AH[2][2], AL[2][2];
        #pragma unroll
        for (int mt = 0; mt < 2; mt++) {
            int r0 = warp_m + mt * 16 + gr;
            AH[mt][0] = *reinterpret_cast<uint4*>(base + r0 * 16 + kq * 4);
            AH[mt][1] = *reinterpret_cast<uint4*>(base + (r0 + 8) * 16 + kq * 4);
            AL[mt][0] = *reinterpret_cast<uint4*>(base + OFF_AL + r0 * 16 + kq * 4);
            AL[mt][1] = *reinterpret_cast<uint4*>(base + OFF_AL + (r0 + 8) * 16 + kq * 4);
        }
        #pragma unroll
        for (int nt = 0; nt < 4; nt++) {
            int c0 = warp_n + nt * 8 + gr;
            uint4 BH = *reinterpret_cast<uint4*>(base + OFF_BH + c0 * 16 + kq * 4);
            uint4 BL = *reinterpret_cast<uint4*>(base + OFF_BL + c0 * 16 + kq * 4);
            #pragma unroll
            for (int mt = 0; mt < 2; mt++) {
                float* d = acc[mt][nt];
                mma_bf16(d, AH[mt][0].x, AH[mt][1].x, AH[mt][0].y, AH[mt][1].y, BH.x, BH.y);
                mma_bf16(d, AH[mt][0].x, AH[mt][1].x, AH[mt][0].y, AH[mt][1].y, BL.x, BL.y);
                mma_bf16(d, AL[mt][0].x, AL[mt][1].x, AL[mt][0].y, AL[mt][1].y, BH.x, BH.y);
                mma_bf16(d, AH[mt][0].z, AH[mt][1].z, AH[mt][0].w, AH[mt][1].w, BH.z, BH.w);
                mma_bf16(d, AH[mt][0].z, AH[mt][1].z, AH[mt][0].w, AH[mt][1].w, BL.z, BL.w);
                mma_bf16(d, AL[mt][0].z, AL[mt][1].z, AL[mt][0].w, AL[mt][1].w, BH.z, BH.w);
            }
        }
        __syncthreads();
    }

    // Epilogue: write Bu to gmem + smem, fused passA (4 chunks of 16 steps).
    float* sbu = reinterpret_cast<float*>(smem_u);
    #pragma unroll
    for (int mt = 0; mt < 2; mt++)
        #pragma unroll
        for (int nt = 0; nt < 4; nt++) {
            int r0 = warp_m + mt * 16 + gr;
            int col = warp_n + nt * 8 + 2 * kq;
            float v00 = acc[mt][nt][0], v01 = acc[mt][nt][1];
            float v10 = acc[mt][nt][2], v11 = acc[mt][nt][3];
            *reinterpret_cast<float2*>(&out[(size_t)(bm + r0) * N + bn + col]) =
                make_float2(v00, v01);
            *reinterpret_cast<float2*>(&out[(size_t)(bm + r0 + 8) * N + bn + col]) =
                make_float2(v10, v11);
            sbu[r0 * SBU_STR + col] = v00;       sbu[r0 * SBU_STR + col + 1] = v01;
            sbu[(r0 + 8) * SBU_STR + col] = v10; sbu[(r0 + 8) * SBU_STR + col + 1] = v11;
        }
    __syncthreads();
    {
        int sl = tid & 63;           // local seq
        int cbase = tid >> 6;        // 0..1 ; handles chunks cbase, cbase+2
        int seq = bn + sl;
        int p = seq & (P_DIM - 1);
        float m11, m12, m21, m22, c1, c2;
        get_consts(A_diag, steps, p, m11, m12, m21, m22, c1, c2);
        #pragma unroll
        for (int j = 0; j < 2; j++) {
            int cc = cbase + j * 2;
            float x1 = 0.0f, x2 = 0.0f;
            #pragma unroll
            for (int s = 0; s < CLEN; s++) {
                float u = sbu[(cc * CLEN + s) * SBU_STR + sl];
                float n1 = fmaf(m11, x1, fmaf(m12, x2, c1 * u));
                float n2 = fmaf(m21, x1, fmaf(m22, x2, c2 * u));
                x1 = n1; x2 = n2;
            }
            g_final[(size_t)seq * NCHUNK + blockIdx.y * 4 + cc] = make_float2(x1, x2);
        }
    }
}

// ---------------------------------------------------------------------------
// Pass B: warp-per-seq shuffle scan over 1024 chunk composites (32 per lane).
__global__ void scan_passB_shfl(const float* __restrict__ A_diag,
                                const float* __restrict__ steps) {
    int seq  = blockIdx.x * 8 + (threadIdx.x >> 5);
    int lane = threadIdx.x & 31;
    int p = seq & (P_DIM - 1);
    float m11, m12, m21, m22, c1u, c2u;
    get_consts(A_diag, steps, p, m11, m12, m21, m22, c1u, c2u);

    // P = M^16 (4 squarings)
    float a = m11, b = m12, c = m21, d = m22;
    #pragma unroll
    for (int i = 0; i < 4; i++) {
        float na = a * a + b * c, nb = a * b + b * d;
        float nc = c * a + d * c, nd = c * b + d * d;
        a = na; b = nb; c = nc; d = nd;
    }

    float2 f[32];
    #pragma unroll
    for (int j = 0; j < 32; j++)
        f[j] = g_final[(size_t)seq * NCHUNK + 32 * lane + j];

    float s1 = f[0].x, s2 = f[0].y;
    #pragma unroll
    for (int j = 1; j < 32; j++) {
        float t1 = fmaf(a, s1, fmaf(b, s2, f[j].x));
        float t2 = fmaf(c, s1, fmaf(d, s2, f[j].y));
        s1 = t1; s2 = t2;
    }

    // Q = P^32 (5 squarings)
    float qa = a, qb = b, qc = c, qd = d;
    #pragma unroll
    for (int i = 0; i < 5; i++) {
        float na = qa * qa + qb * qc, nb = qa * qb + qb * qd;
        float nc = qc * qa + qd * qc, nd = qc * qb + qd * qd;
        qa = na; qb = nb; qc = nc; qd = nd;
    }

    #pragma unroll
    for (int dstep = 1; dstep < 32; dstep <<= 1) {
        float u1 = __shfl_up_sync(0xffffffffu, s1, dstep);
        float u2 = __shfl_up_sync(0xffffffffu, s2, dstep);
        if (lane >= dstep) {
            s1 = fmaf(qa, u1, fmaf(qb, u2, s1));
            s2 = fmaf(qc, u1, fmaf(qd, u2, s2));
        }
        float na = qa * qa + qb * qc, nb = qa * qb + qb * qd;
        float nc = qc * qa + qd * qc, nd = qc * qb + qd * qd;
        qa = na; qb = nb; qc = nc; qd = nd;
    }

    float e1 = __shfl_up_sync(0xffffffffu, s1, 1);
    float e2 = __shfl_up_sync(0xffffffffu, s2, 1);
    if (lane == 0) { e1 = 0.0f; e2 = 0.0f; }

    g_initv[(size_t)(32 * lane) * NSEQ + seq] = make_float2(e1, e2);
    #pragma unroll
    for (int j = 1; j < 32; j++) {
        float t1 = fmaf(a, e1, fmaf(b, e2, f[j - 1].x));
        float t2 = fmaf(c, e1, fmaf(d, e2, f[j - 1].y));
        e1 = t1; e2 = t2;
        g_initv[(size_t)(32 * lane + j) * NSEQ + seq] = make_float2(e1, e2);
    }
}

// ---------------------------------------------------------------------------
// GEMM2 with fused passC. BM=64 (4 chunks x 16), BN=64, 128 threads, grid
// (2, 256) -> 512 blocks. Per k-tile (32 seqs): load Bu tile, scan in smem
// emitting bf16 hi/lo, then MMA. smem/stage (u32):
//   BU 64x36=2304 | XH 1024 | XL 1024 | WH 1024 | WL 1024 = 6400 (25.6KB)
#define G2_BU 0
#define G2_XH 2304
#define G2_XL 3328
#define G2_WH 4352
#define G2_WL 5376
#define G2_STAGE 6400
#define BU_STR 36

__global__ void __launch_bounds__(128)
gemm2_fused(const uint32_t* __restrict__ WH_g, const uint32_t* __restrict__ WL_g,
            const float* __restrict__ bu_g, float* __restrict__ out,
            const float* __restrict__ resid, const float* __restrict__ Dv,
            const float* __restrict__ A_diag, const float* __restrict__ steps) {
    extern __shared__ uint32_t smem_u[];
    const int N = H_DIM;
    const int tid  = threadIdx.x;
    const int lane = tid & 31;
    const int wid  = tid >> 5;
    const int warp_m = (wid & 1) * 32;
    const int warp_n = (wid >> 1) * 32;
    const int gr = lane >> 2;
    const int kq = lane & 3;
    const int by = blockIdx.y;
    const int bm = by * 64, bn = blockIdx.x * 64;

    float acc[2][4][4];
    #pragma unroll
    for (int i = 0; i < 2; i++)
        #pragma unroll
        for (int j = 0; j < 4; j++)
            #pragma unroll
            for (int q = 0; q < 4; q++) acc[i][j][q] = 0.0f;

    auto load_tile = [&](int kt, int s) {
        uint32_t* base = smem_u + s * G2_STAGE;
        #pragma unroll
        for (int it = 0; it < 4; it++) {       // Bu: 64 rows x 32 floats
            int id = tid + it * 128;
            int r = id >> 3, c4 = (id & 7) << 2;
            CP16((uint32_t)__cvta_generic_to_shared(base + G2_BU + r * BU_STR + c4),
                 bu_g + (size_t)(bm + r) * NSEQ + kt * 32 + c4);
        }
        #pragma unroll
        for (int it = 0; it < 2; it++) {       // W2: 64 rows x 16 u32 (hi & lo)
            int id = tid + it * 128;
            int r = id >> 2, c4 = (id & 3) << 2;
            CP16((uint32_t)__cvta_generic_to_shared(base + G2_WH + r * 16 + c4),
                 WH_g + (size_t)(bn + r) * 256 + kt * 16 + c4);
            CP16((uint32_t)__cvta_generic_to_shared(base + G2_WL + r * 16 + c4),
                 WL_g + (size_t)(bn + r) * 256 + kt * 16 + c4);
        }
    };

    auto scan_tile = [&](int kt, int s) {
        uint32_t* base = smem_u + s * G2_STAGE;
        int sl = tid & 31;                 // local seq
        int cc = tid >> 5;                 // chunk 0..3
        int seq = kt * 32 + sl;
        int p = seq & (P_DIM - 1);
        float m11, m12, m21, m22, c1, c2;
        get_consts(A_diag, steps, p, m11, m12, m21, m22, c1, c2);
        float2 ini = g_initv[(size_t)(by * 4 + cc) * NSEQ + seq];
        float x1 = ini.x, x2 = ini.y;
        const float* bu = reinterpret_cast<const float*>(base + G2_BU)
                          + cc * CLEN * BU_STR + sl;
        __nv_bfloat16* ah = reinterpret_cast<__nv_bfloat16*>(base + G2_XH);
        __nv_bfloat16* al = reinterpret_cast<__nv_bfloat16*>(base + G2_XL);
        int pi = sl >> 1, half = sl & 1;
        int slot = ((pi & 3) << 2) | (pi >> 2);
        #pragma unroll
        for (int st = 0; st < CLEN; st++) {
            float u = bu[st * BU_STR];
            float n1 = fmaf(m11, x1, fmaf(m12, x2, c1 * u));
            float n2 = fmaf(m21, x1, fmaf(m22, x2, c2 * u));
            x1 = n1; x2 = n2;
            int row = cc * CLEN + st;
            __nv_bfloat16 h = __float2bfloat16_rn(x2);
            ah[(row * 16 + slot) * 2 + half] = h;
            al[(row * 16 + slot) * 2 + half] =
                __float2bfloat16_rn(x2 - __bfloat162float(h));
        }
    };

    load_tile(0, 0);
    asm volatile("cp.async.commit_group;\n");
    asm volatile("cp.async.wait_group 0;\n");
    __syncthreads();
    scan_tile(0, 0);
    __syncthreads();

    for (int kt = 0; kt < 16; kt++) {
        int s = kt & 1;
        if (kt < 15) {
            load_tile(kt + 1, s ^ 1);
            asm volatile("cp.async.commit_group;\n");
        }
        uint32_t* base = smem_u + s * G2_STAGE;
        uint4 AH[2][2], AL[2][2];
        #pragma unroll
        for (int mt = 0; mt < 2; mt++) {
            int r0 = warp_m + mt * 16 + gr;
            AH[mt][0] = *reinterpret_cast<uint4*>(base + G2_XH + r0 * 16 + kq * 4);
            AH[mt][1] = *reinterpret_cast<uint4*>(base + G2_XH + (r0 + 8) * 16 + kq * 4);
            AL[mt][0] = *reinterpret_cast<uint4*>(base + G2_XL + r0 * 16 + kq * 4);
            AL[mt][1] = *reinterpret_cast<uint4*>(base + G2_XL + (r0 + 8) * 16 + kq * 4);
        }
        #pragma unroll
        for (int nt = 0; nt < 4; nt++) {
            int c0 = warp_n + nt * 8 + gr;
            uint4 BH = *reinterpret_cast<uint4*>(base + G2_WH + c0 * 16 + kq * 4);
            uint4 BL = *reinterpret_cast<uint4*>(base + G2_WL + c0 * 16 + kq * 4);
            #pragma unroll
            for (int mt = 0; mt < 2; mt++) {
                float* d = acc[mt][nt];
                mma_bf16(d, AH[mt][0].x, AH[mt][1].x, AH[mt][0].y, AH[mt][1].y, BH.x, BH.y);
                mma_bf16(d, AH[mt][0].x, AH[mt][1].x, AH[mt][0].y, AH[mt][1].y, BL.x, BL.y);
                mma_bf16(d, AL[mt][0].x, AL[mt][1].x, AL[mt][0].y, AL[mt][1].y, BH.x, BH.y);
                mma_bf16(d, AH[mt][0].z, AH[mt][1].z, AH[mt][0].w, AH[mt][1].w, BH.z, BH.w);
                mma_bf16(d, AH[mt][0].z, AH[mt][1].z, AH[mt][0].w, AH[mt][1].w, BL.z, BL.w);
                mma_bf16(d, AL[mt][0].z, AL[mt][1].z, AL[mt][0].w, AL[mt][1].w, BH.z, BH.w);
            }
        }
        if (kt < 15) {
            asm volatile("cp.async.wait_group 0;\n");
            __syncthreads();
            scan_tile(kt + 1, s ^ 1);
            __syncthreads();
        }
    }

    // Epilogue: out = acc + resid * D
    #pragma unroll
    for (int mt = 0; mt < 2; mt++)
        #pragma unroll
        for (int nt = 0; nt < 4; nt++) {
            int row = bm + warp_m + mt * 16 + gr;
            int col = bn + warp_n + nt * 8 + 2 * kq;
            float2 v0 = make_float2(acc[mt][nt][0], acc[mt][nt][1]);
            float2 v1 = make_float2(acc[mt][nt][2], acc[mt][nt][3]);
            float2 r0 = *reinterpret_cast<const float2*>(&resid[(size_t)row * N + col]);
            float2 r1 = *reinterpret_cast<const float2*>(&resid[(size_t)(row + 8) * N + col]);
            float d0 = Dv[col], d1 = Dv[col + 1];
            v0.x += r0.x * d0; v0.y += r0.y * d1;
            v1.x += r1.x * d0; v1.y += r1.y * d1;
            *reinterpret_cast<float2*>(&out[(size_t)row * N + col]) = v0;
            *reinterpret_cast<float2*>(&out[(size_t)(row + 8) * N + col]) = v1;
        }
}

// ---------------------------------------------------------------------------
extern "C" void kernel_launch(void* const* d_in, const int* in_sizes, int n_in,
                              void* d_out, int out_size) {
    const float* input  = (const float*)d_in[0];  // (L, H)
    const float* A_diag = (const float*)d_in[1];  // (P,)
    const float* B      = (const float*)d_in[2];  // (P, H, 2)
    const float* C      = (const float*)d_in[3];  // (H, P, 2)
    const float* D      = (const float*)d_in[4];  // (H,)
    const float* steps  = (const float*)d_in[5];  // (P,)
    float* out = (float*)d_out;                   // (L, H)

    float *p_bu;
    uint32_t *p_inH, *p_inL, *p_w1H, *p_w1L, *p_w2H, *p_w2L;
    cudaGetSymbolAddress((void**)&p_bu,  g_buall);
    cudaGetSymbolAddress((void**)&p_inH, g_inH);
    cudaGetSymbolAddress((void**)&p_inL, g_inL);
    cudaGetSymbolAddress((void**)&p_w1H, g_W1H);
    cudaGetSymbolAddress((void**)&p_w1L, g_W1L);
    cudaGetSymbolAddress((void**)&p_w2H, g_W2H);
    cudaGetSymbolAddress((void**)&p_w2L, g_W2L);

    const int dyn1 = STAGE_U * 2 * sizeof(uint32_t);   // 32768
    const int dyn2 = G2_STAGE * 2 * sizeof(uint32_t);  // 51200
    cudaFuncSetAttribute(gemm1_fused,
                         cudaFuncAttributeMaxDynamicSharedMemorySize, dyn1);
    cudaFuncSetAttribute(gemm2_fused,
                         cudaFuncAttributeMaxDynamicSharedMemorySize, dyn2);

    prep_all<<<L_SEQ * 64 / 256, 256>>>(input, B, C);

    // GEMM1 + fused passA: Bu = input @ W1^T  (16384 x 512, K=128)
    gemm1_fused<<<dim3(NSEQ / 64, L_SEQ / 64), 128, dyn1>>>(
        p_inH, p_inL, p_w1H, p_w1L, p_bu, A_diag, steps);

    scan_passB_shfl<<<NSEQ / 8, 256>>>(A_diag, steps);

    // GEMM2 + fused passC: ys = x2 @ W2^T + input * D
    gemm2_fused<<<dim3(2, L_SEQ / 64), 128, dyn2>>>(
        p_w2H, p_w2L, p_bu, out, input, D, A_diag, steps);
}

// round 14
// speedup vs baseline: 1.0597x; 1.0597x over previous
#include <cuda_runtime.h>
#include <cuda_bf16.h>
#include <math.h>
#include <stdint.h>

#define L_SEQ 16384
#define H_DIM 128
#define P_DIM 256
#define NSEQ  512          // 256 channels x {re, im}
#define NCHUNK 512
#define CLEN   32          // NCHUNK * CLEN == L_SEQ

// ---------------------------------------------------------------------------
// Scratch (device globals)
__device__ float    g_buall[L_SEQ * NSEQ];        // fp32 Bu (for passC)
__device__ uint32_t g_inH[L_SEQ * (H_DIM / 2)];   // input hi bf16-pairs, permuted
__device__ uint32_t g_inL[L_SEQ * (H_DIM / 2)];
__device__ uint32_t g_W1H[NSEQ * (H_DIM / 2)];    // [Br;Bi]
__device__ uint32_t g_W1L[NSEQ * (H_DIM / 2)];
__device__ uint32_t g_W2H[H_DIM * (NSEQ / 2)];    // [Cr,-Ci]
__device__ uint32_t g_W2L[H_DIM * (NSEQ / 2)];
__device__ uint32_t g_x2H[L_SEQ * (NSEQ / 2)];    // x2 split, permuted
__device__ uint32_t g_x2L[L_SEQ * (NSEQ / 2)];
__device__ float2   g_final[NSEQ * NCHUNK];       // [seq][chunk]
__device__ float2   g_initv[NCHUNK * NSEQ];       // [chunk][seq]

// ---------------------------------------------------------------------------
__device__ __forceinline__ uint32_t packbf(float lo, float hi) {  // lo -> bits[15:0]
    uint32_t r;
    asm("cvt.rn.bf16x2.f32 %0, %1, %2;" : "=r"(r) : "f"(hi), "f"(lo));
    return r;
}
__device__ __forceinline__ int pair_pos(int P) {  // permute pairs within 16-pair groups
    int pi = P & 15;
    return (P & ~15) | (((pi & 3) << 2) | (pi >> 2));
}
__device__ __forceinline__ float bfhi(float v) {
    return __bfloat162float(__float2bfloat16_rn(v));
}
__device__ __forceinline__ void mma_bf16(float* d, uint32_t a0, uint32_t a1,
                                         uint32_t a2, uint32_t a3,
                                         uint32_t b0, uint32_t b1) {
    asm volatile(
        "mma.sync.aligned.m16n8k16.row.col.f32.bf16.bf16.f32 "
        "{%0,%1,%2,%3},{%4,%5,%6,%7},{%8,%9},{%0,%1,%2,%3};\n"
        : "+f"(d[0]), "+f"(d[1]), "+f"(d[2]), "+f"(d[3])
        : "r"(a0), "r"(a1), "r"(a2), "r"(a3), "r"(b0), "r"(b1));
}
#define CP16(dst_u32, src_ptr) \
    asm volatile("cp.async.cg.shared.global [%0], [%1], 16;\n" :: "r"(dst_u32), "l"(src_ptr))

// ---------------------------------------------------------------------------
// Merged prep: input split (L*64 pair-slots) + both weight packs.
__global__ void prep_all(const float* __restrict__ in, const float* __restrict__ B,
                         const float* __restrict__ C) {
    int i = blockIdx.x * blockDim.x + threadIdx.x;   // 0 .. L*64-1
    {   // input
        int row = i >> 6, P = i & 63;
        float v0 = in[row * 128 + 2 * P];
        float v1 = in[row * 128 + 2 * P + 1];
        float h0 = bfhi(v0), h1 = bfhi(v1);
        int col = pair_pos(P);
        g_inH[row * 64 + col] = packbf(h0, h1);
        g_inL[row * 64 + col] = packbf(v0 - h0, v1 - h1);
    }
    if (i < NSEQ * 64) {   // W1: rows 0..511, 64 pairs
        int row = i >> 6, P = i & 63;
        float v0, v1;
        if (row < P_DIM) {
            v0 = B[(row * H_DIM + 2 * P) * 2 + 0];
            v1 = B[(row * H_DIM + 2 * P + 1) * 2 + 0];
        } else {
            int r = row - P_DIM;
            v0 = B[(r * H_DIM + 2 * P) * 2 + 1];
            v1 = B[(r * H_DIM + 2 * P + 1) * 2 + 1];
        }
        float h0 = bfhi(v0), h1 = bfhi(v1);
        int col = pair_pos(P);
        g_W1H[row * 64 + col] = packbf(h0, h1);
        g_W1L[row * 64 + col] = packbf(v0 - h0, v1 - h1);
    }
    if (i < H_DIM * 256) {  // W2: rows 0..127, 256 pairs
        int row = i >> 8, P = i & 255;
        int k0 = 2 * P;
        float v0, v1;
        if (k0 < P_DIM) {
            v0 =  C[(row * P_DIM + k0) * 2 + 0];
            v1 =  C[(row * P_DIM + k0 + 1) * 2 + 0];
        } else {
            v0 = -C[(row * P_DIM + k0 - P_DIM) * 2 + 1];
            v1 = -C[(row * P_DIM + k0 + 1 - P_DIM) * 2 + 1];
        }
        float h0 = bfhi(v0), h1 = bfhi(v1);
        int col = pair_pos(P);
        g_W2H[row * 256 + col] = packbf(h0, h1);
        g_W2L[row * 256 + col] = packbf(v0 - h0, v1 - h1);
    }
}

// ---------------------------------------------------------------------------
__device__ __forceinline__ void get_consts(const float* __restrict__ A_diag,
                                           const float* __restrict__ steps, int p,
                                           float& m11, float& m12, float& m21, float& m22,
                                           float& c1, float& c2) {
    float A  = fmaxf(A_diag[p], 0.0f);
    float dt = 1.0f / (1.0f + __expf(-steps[p]));
    float schur = 1.0f / (1.0f + dt * dt * A);
    m11 = 1.0f - dt * dt * A * schur;
    m12 = -dt * A * schur;
    m21 = dt * schur;
    m22 = schur;
    c1 = m11 * dt;
    c2 = m21 * dt;
}

// ---------------------------------------------------------------------------
// 3xBF16 NT GEMM. BM=64, BN=64, BK=64 (two 32-k sub-tiles per stage),
// 128 threads (4 warps 2x2, warp tile 32x32).
// smem/stage (u32): per half 1024 each of AH|AL|BH|BL -> 8192 (32KB); 2 stages.
#define OFF_AL 2048
#define OFF_BH 4096
#define OFF_BL 6144
#define STAGE_U 8192
#define SBU_STR 65

template <bool FUSE, bool EPI>
__global__ void __launch_bounds__(128)
gemm_bf16x3(const uint32_t* __restrict__ AH_g, const uint32_t* __restrict__ AL_g,
            const uint32_t* __restrict__ BH_g, const uint32_t* __restrict__ BL_g,
            float* __restrict__ out, int M, int N, int K,
            const float* __restrict__ resid, const float* __restrict__ Dv,
            const float* __restrict__ A_diag, const float* __restrict__ steps) {
    extern __shared__ uint32_t smem_u[];
    const int tid  = threadIdx.x;
    const int lane = tid & 31;
    const int wid  = tid >> 5;
    const int warp_m = (wid & 1) * 32;
    const int warp_n = (wid >> 1) * 32;
    const int gr = lane >> 2;
    const int kq = lane & 3;
    const int bm = blockIdx.y * 64, bn = blockIdx.x * 64;
    const int KW = K >> 1;

    float acc[2][4][4];
    #pragma unroll
    for (int i = 0; i < 2; i++)
        #pragma unroll
        for (int j = 0; j < 4; j++)
            #pragma unroll
            for (int q = 0; q < 4; q++) acc[i][j][q] = 0.0f;

    const int nk = K >> 6;    // 64-k tiles

    auto stage_load = [&](int kt, int s) {
        uint32_t* base = smem_u + s * STAGE_U;
        #pragma unroll
        for (int h = 0; h < 2; h++) {
            int kofs = (kt << 5) + (h << 4);
            uint32_t ho = h << 10;                 // h * 1024
            #pragma unroll
            for (int it = 0; it < 2; it++) {
                int id = tid + it * 128;
                int r = id >> 2, c4 = (id & 3) << 2;
                CP16((uint32_t)__cvta_generic_to_shared(base + ho + r * 16 + c4),
                     AH_g + (size_t)(bm + r) * KW + kofs + c4);
                CP16((uint32_t)__cvta_generic_to_shared(base + OFF_AL + ho + r * 16 + c4),
                     AL_g + (size_t)(bm + r) * KW + kofs + c4);
                CP16((uint32_t)__cvta_generic_to_shared(base + OFF_BH + ho + r * 16 + c4),
                     BH_g + (size_t)(bn + r) * KW + kofs + c4);
                CP16((uint32_t)__cvta_generic_to_shared(base + OFF_BL + ho + r * 16 + c4),
                     BL_g + (size_t)(bn + r) * KW + kofs + c4);
            }
        }
    };

    stage_load(0, 0);
    asm volatile("cp.async.commit_group;\n");

    for (int kt = 0; kt < nk; kt++) {
        int s = kt & 1;
        if (kt + 1 < nk) stage_load(kt + 1, s ^ 1);
        asm volatile("cp.async.commit_group;\n");
        asm volatile("cp.async.wait_group 1;\n");
        __syncthreads();

        uint32_t* base = smem_u + s * STAGE_U;
        #pragma unroll
        for (int h = 0; h < 2; h++) {
            uint32_t ho = h << 10;
            uint4 AH[2][2], AL[2][2];
            #pragma unroll
            for (int mt = 0; mt < 2; mt++) {
                int r0 = warp_m + mt * 16 + gr;
                AH[mt][0] = *reinterpret_cast<uint4*>(base + ho + r0 * 16 + kq * 4);
                AH[mt][1] = *reinterpret_cast<uint4*>(base + ho + (r0 + 8) * 16 + kq * 4);
                AL[mt][0] = *reinterpret_cast<uint4*>(base + OFF_AL + ho + r0 * 16 + kq * 4);
                AL[mt][1] = *reinterpret_cast<uint4*>(base + OFF_AL + ho + (r0 + 8) * 16 + kq * 4);
            }
            #pragma unroll
            for (int nt = 0; nt < 4; nt++) {
                int c0 = warp_n + nt * 8 + gr;
                uint4 BH = *reinterpret_cast<uint4*>(base + OFF_BH + ho + c0 * 16 + kq * 4);
                uint4 BL = *reinterpret_cast<uint4*>(base + OFF_BL + ho + c0 * 16 + kq * 4);
                #pragma unroll
                for (int mt = 0; mt < 2; mt++) {
                    float* d = acc[mt][nt];
                    mma_bf16(d, AH[mt][0].x, AH[mt][1].x, AH[mt][0].y, AH[mt][1].y, BH.x, BH.y);
                    mma_bf16(d, AH[mt][0].x, AH[mt][1].x, AH[mt][0].y, AH[mt][1].y, BL.x, BL.y);
                    mma_bf16(d, AL[mt][0].x, AL[mt][1].x, AL[mt][0].y, AL[mt][1].y, BH.x, BH.y);
                    mma_bf16(d, AH[mt][0].z, AH[mt][1].z, AH[mt][0].w, AH[mt][1].w, BH.z, BH.w);
                    mma_bf16(d, AH[mt][0].z, AH[mt][1].z, AH[mt][0].w, AH[mt][1].w, BL.z, BL.w);
                    mma_bf16(d, AL[mt][0].z, AL[mt][1].z, AL[mt][0].w, AL[mt][1].w, BH.z, BH.w);
                }
            }
        }
        __syncthreads();
    }

    // ---------------- Epilogue ----------------
    if (FUSE) {
        // write Bu to gmem + smem (stride 65); fused passA: 64 seqs x 2 chunks.
        float* sbu = reinterpret_cast<float*>(smem_u);
        #pragma unroll
        for (int mt = 0; mt < 2; mt++)
            #pragma unroll
            for (int nt = 0; nt < 4; nt++) {
                int r0 = warp_m + mt * 16 + gr;
                int col = warp_n + nt * 8 + 2 * kq;
                float v00 = acc[mt][nt][0], v01 = acc[mt][nt][1];
                float v10 = acc[mt][nt][2], v11 = acc[mt][nt][3];
                *reinterpret_cast<float2*>(&out[(size_t)(bm + r0) * N + bn + col]) =
                    make_float2(v00, v01);
                *reinterpret_cast<float2*>(&out[(size_t)(bm + r0 + 8) * N + bn + col]) =
                    make_float2(v10, v11);
                sbu[r0 * SBU_STR + col] = v00;       sbu[r0 * SBU_STR + col + 1] = v01;
                sbu[(r0 + 8) * SBU_STR + col] = v10; sbu[(r0 + 8) * SBU_STR + col + 1] = v11;
            }
        __syncthreads();
        {
            int sl = tid & 63;           // local seq
            int cc = tid >> 6;           // sub-chunk 0..1
            int seq = bn + sl;
            int p = seq & (P_DIM - 1);
            float m11, m12, m21, m22, c1, c2;
            get_consts(A_diag, steps, p, m11, m12, m21, m22, c1, c2);
            float x1 = 0.0f, x2 = 0.0f;
            #pragma unroll 8
            for (int s = 0; s < CLEN; s++) {
                float u = sbu[(cc * CLEN + s) * SBU_STR + sl];
                float n1 = fmaf(m11, x1, fmaf(m12, x2, c1 * u));
                float n2 = fmaf(m21, x1, fmaf(m22, x2, c2 * u));
                x1 = n1; x2 = n2;
            }
            g_final[(size_t)seq * NCHUNK + blockIdx.y * 2 + cc] = make_float2(x1, x2);
        }
    } else {
        #pragma unroll
        for (int mt = 0; mt < 2; mt++)
            #pragma unroll
            for (int nt = 0; nt < 4; nt++) {
                int row = bm + warp_m + mt * 16 + gr;
                int col = bn + warp_n + nt * 8 + 2 * kq;
                float2 v0 = make_float2(acc[mt][nt][0], acc[mt][nt][1]);
                float2 v1 = make_float2(acc[mt][nt][2], acc[mt][nt][3]);
                if (EPI) {
                    float2 r0 = *reinterpret_cast<const float2*>(&resid[(size_t)row * N + col]);
                    float2 r1 = *reinterpret_cast<const float2*>(&resid[(size_t)(row + 8) * N + col]);
                    float d0 = Dv[col], d1 = Dv[col + 1];
                    v0.x += r0.x * d0; v0.y += r0.y * d1;
                    v1.x += r1.x * d0; v1.y += r1.y * d1;
                }
                *reinterpret_cast<float2*>(&out[(size_t)row * N + col]) = v0;
                *reinterpret_cast<float2*>(&out[(size_t)(row + 8) * N + col]) = v1;
            }
    }
}

// ---------------------------------------------------------------------------
// Pass B: warp-per-seq shuffle scan over 512 chunk composites (16 per lane).
__global__ void scan_passB_shfl(const float* __restrict__ A_diag,
                                const float* __restrict__ steps) {
    int seq  = blockIdx.x * 8 + (threadIdx.x >> 5);
    int lane = threadIdx.x & 31;
    int p = seq & (P_DIM - 1);
    float m11, m12, m21, m22, c1u, c2u;
    get_consts(A_diag, steps, p, m11, m12, m21, m22, c1u, c2u);

    // P = M^32 (5 squarings)
    float a = m11, b = m12, c = m21, d = m22;
    #pragma unroll
    for (int i = 0; i < 5; i++) {
        float na = a * a + b * c, nb = a * b + b * d;
        float nc = c * a + d * c, nd = c * b + d * d;
        a = na; b = nb; c = nc; d = nd;
    }

    float2 f[16];
    #pragma unroll
    for (int j = 0; j < 16; j++)
        f[j] = g_final[(size_t)seq * NCHUNK + 16 * lane + j];

    float s1 = f[0].x, s2 = f[0].y;
    #pragma unroll
    for (int j = 1; j < 16; j++) {
        float t1 = fmaf(a, s1, fmaf(b, s2, f[j].x));
        float t2 = fmaf(c, s1, fmaf(d, s2, f[j].y));
        s1 = t1; s2 = t2;
    }

    // Q = P^16 (4 squarings)
    float qa = a, qb = b, qc = c, qd = d;
    #pragma unroll
    for (int i = 0; i < 4; i++) {
        float na = qa * qa + qb * qc, nb = qa * qb + qb * qd;
        float nc = qc * qa + qd * qc, nd = qc * qb + qd * qd;
        qa = na; qb = nb; qc = nc; qd = nd;
    }

    #pragma unroll
    for (int dstep = 1; dstep < 32; dstep <<= 1) {
        float u1 = __shfl_up_sync(0xffffffffu, s1, dstep);
        float u2 = __shfl_up_sync(0xffffffffu, s2, dstep);
        if (lane >= dstep) {
            s1 = fmaf(qa, u1, fmaf(qb, u2, s1));
            s2 = fmaf(qc, u1, fmaf(qd, u2, s2));
        }
        float na = qa * qa + qb * qc, nb = qa * qb + qb * qd;
        float nc = qc * qa + qd * qc, nd = qc * qb + qd * qd;
        qa = na; qb = nb; qc = nc; qd = nd;
    }

    float e1 = __shfl_up_sync(0xffffffffu, s1, 1);
    float e2 = __shfl_up_sync(0xffffffffu, s2, 1);
    if (lane == 0) { e1 = 0.0f; e2 = 0.0f; }

    g_initv[(size_t)(16 * lane) * NSEQ + seq] = make_float2(e1, e2);
    #pragma unroll
    for (int j = 1; j < 16; j++) {
        float t1 = fmaf(a, e1, fmaf(b, e2, f[j - 1].x));
        float t2 = fmaf(c, e1, fmaf(d, e2, f[j - 1].y));
        e1 = t1; e2 = t2;
        g_initv[(size_t)(16 * lane + j) * NSEQ + seq] = make_float2(e1, e2);
    }
}

// ---------------------------------------------------------------------------
// Pass C: 2 seqs/thread, explicit 8-deep load prefetch ring; u32 pair stores.
__global__ void __launch_bounds__(256)
scan_passC(const float* __restrict__ A_diag, const float* __restrict__ steps) {
    int t = threadIdx.x;               // 0..255 ; seqs 2t, 2t+1
    int c = blockIdx.x;                // chunk 0..511
    int s0 = 2 * t, s1 = 2 * t + 1;
    float a11, a12, a21, a22, ac1, ac2;
    float b11, b12, b21, b22, bc1, bc2;
    get_consts(A_diag, steps, s0 & (P_DIM - 1), a11, a12, a21, a22, ac1, ac2);
    get_consts(A_diag, steps, s1 & (P_DIM - 1), b11, b12, b21, b22, bc1, bc2);

    float2 i0 = g_initv[(size_t)c * NSEQ + s0];
    float2 i1 = g_initv[(size_t)c * NSEQ + s1];
    float x1a = i0.x, x2a = i0.y, x1b = i1.x, x2b = i1.y;

    int col = pair_pos(t);
    const float* bu = g_buall + (size_t)c * CLEN * NSEQ + s0;
    uint32_t* xh = g_x2H + (size_t)c * CLEN * 256 + col;
    uint32_t* xl = g_x2L + (size_t)c * CLEN * 256 + col;

    // 8-deep prefetch ring: force outstanding loads ahead of the serial chain.
    float2 ubuf[8];
    #pragma unroll
    for (int j = 0; j < 8; j++)
        ubuf[j] = *reinterpret_cast<const float2*>(bu + (size_t)j * NSEQ);

    #pragma unroll
    for (int s = 0; s < CLEN; s++) {
        float2 u = ubuf[s & 7];
        if (s + 8 < CLEN)
            ubuf[s & 7] = *reinterpret_cast<const float2*>(bu + (size_t)(s + 8) * NSEQ);
        float n1a = fmaf(a11, x1a, fmaf(a12, x2a, ac1 * u.x));
        float n2a = fmaf(a21, x1a, fmaf(a22, x2a, ac2 * u.x));
        float n1b = fmaf(b11, x1b, fmaf(b12, x2b, bc1 * u.y));
        float n2b = fmaf(b21, x1b, fmaf(b22, x2b, bc2 * u.y));
        x1a = n1a; x2a = n2a; x1b = n1b; x2b = n2b;
        float h0 = bfhi(x2a), h1 = bfhi(x2b);
        xh[(size_t)s * 256] = packbf(h0, h1);
        xl[(size_t)s * 256] = packbf(x2a - h0, x2b - h1);
    }
}

// ---------------------------------------------------------------------------
extern "C" void kernel_launch(void* const* d_in, const int* in_sizes, int n_in,
                              void* d_out, int out_size) {
    const float* input  = (const float*)d_in[0];  // (L, H)
    const float* A_diag = (const float*)d_in[1];  // (P,)
    const float* B      = (const float*)d_in[2];  // (P, H, 2)
    const float* C      = (const float*)d_in[3];  // (H, P, 2)
    const float* D      = (const float*)d_in[4];  // (H,)
    const float* steps  = (const float*)d_in[5];  // (P,)
    float* out = (float*)d_out;                   // (L, H)

    float *p_bu;
    uint32_t *p_inH, *p_inL, *p_w1H, *p_w1L, *p_w2H, *p_w2L, *p_x2H, *p_x2L;
    cudaGetSymbolAddress((void**)&p_bu,  g_buall);
    cudaGetSymbolAddress((void**)&p_inH, g_inH);
    cudaGetSymbolAddress((void**)&p_inL, g_inL);
    cudaGetSymbolAddress((void**)&p_w1H, g_W1H);
    cudaGetSymbolAddress((void**)&p_w1L, g_W1L);
    cudaGetSymbolAddress((void**)&p_w2H, g_W2H);
    cudaGetSymbolAddress((void**)&p_w2L, g_W2L);
    cudaGetSymbolAddress((void**)&p_x2H, g_x2H);
    cudaGetSymbolAddress((void**)&p_x2L, g_x2L);

    const int dyn = STAGE_U * 2 * sizeof(uint32_t);   // 65536 bytes
    cudaFuncSetAttribute(gemm_bf16x3<true, false>,
                         cudaFuncAttributeMaxDynamicSharedMemorySize, dyn);
    cudaFuncSetAttribute(gemm_bf16x3<false, true>,
                         cudaFuncAttributeMaxDynamicSharedMemorySize, dyn);

    prep_all<<<L_SEQ * 64 / 256, 256>>>(input, B, C);

    // GEMM1 + fused passA: Bu = input @ W1^T  (16384 x 512, K=128)
    gemm_bf16x3<true, false><<<dim3(NSEQ / 64, L_SEQ / 64), 128, dyn>>>(
        p_inH, p_inL, p_w1H, p_w1L, p_bu, L_SEQ, NSEQ, H_DIM,
        nullptr, nullptr, A_diag, steps);

    scan_passB_shfl<<<NSEQ / 8, 256>>>(A_diag, steps);
    scan_passC<<<NCHUNK, 256>>>(A_diag, steps);

    // GEMM2: ys = x2 @ W2^T + input * D  (16384 x 128, K=512)
    gemm_bf16x3<false, true><<<dim3(H_DIM / 64, L_SEQ / 64), 128, dyn>>>(
        p_x2H, p_x2L, p_w2H, p_w2L, out, L_SEQ, H_DIM, NSEQ,
        input, D, nullptr, nullptr);
}

// round 16
// speedup vs baseline: 1.3181x; 1.2439x over previous
#include <cuda_runtime.h>
#include <cuda_fp16.h>
#include <math.h>
#include <stdint.h>

#define L_SEQ 16384
#define H_DIM 128
#define P_DIM 256
#define NSEQ  512          // 256 channels x {re, im}
#define NCHUNK 512
#define CLEN   32          // NCHUNK * CLEN == L_SEQ

// ---------------------------------------------------------------------------
// Scratch (device globals)
__device__ float    g_buall[L_SEQ * NSEQ];        // fp32 Bu (for passC)
__device__ uint32_t g_inH[L_SEQ * (H_DIM / 2)];   // input hi fp16-pairs, permuted
__device__ uint32_t g_inL[L_SEQ * (H_DIM / 2)];   // input lo fp16-pairs
__device__ uint32_t g_W1H[NSEQ * (H_DIM / 2)];    // [Br;Bi] fp16 (single term)
__device__ uint32_t g_W2H[H_DIM * (NSEQ / 2)];    // [Cr,-Ci] fp16 (single term)
__device__ uint32_t g_x2H[L_SEQ * (NSEQ / 2)];    // x2 hi fp16, permuted
__device__ uint32_t g_x2L[L_SEQ * (NSEQ / 2)];    // x2 lo fp16
__device__ float2   g_final[NSEQ * NCHUNK];       // [seq][chunk]
__device__ float2   g_initv[NCHUNK * NSEQ];       // [chunk][seq]

// ---------------------------------------------------------------------------
__device__ __forceinline__ uint32_t packh(float lo, float hi) {  // lo -> bits[15:0]
    uint32_t r;
    asm("cvt.rn.f16x2.f32 %0, %1, %2;" : "=r"(r) : "f"(hi), "f"(lo));
    return r;
}
__device__ __forceinline__ int pair_pos(int P) {  // permute pairs within 16-pair groups
    int pi = P & 15;
    return (P & ~15) | (((pi & 3) << 2) | (pi >> 2));
}
__device__ __forceinline__ float f16hi(float v) {
    return __half2float(__float2half_rn(v));
}
__device__ __forceinline__ void mma_f16(float* d, uint32_t a0, uint32_t a1,
                                        uint32_t a2, uint32_t a3,
                                        uint32_t b0, uint32_t b1) {
    asm volatile(
        "mma.sync.aligned.m16n8k16.row.col.f32.f16.f16.f32 "
        "{%0,%1,%2,%3},{%4,%5,%6,%7},{%8,%9},{%0,%1,%2,%3};\n"
        : "+f"(d[0]), "+f"(d[1]), "+f"(d[2]), "+f"(d[3])
        : "r"(a0), "r"(a1), "r"(a2), "r"(a3), "r"(b0), "r"(b1));
}
#define CP16(dst_u32, src_ptr) \
    asm volatile("cp.async.cg.shared.global [%0], [%1], 16;\n" :: "r"(dst_u32), "l"(src_ptr))

// ---------------------------------------------------------------------------
// Merged prep: input split (hi+lo) + W1/W2 single-term fp16 packs.
__global__ void prep_all(const float* __restrict__ in, const float* __restrict__ B,
                         const float* __restrict__ C) {
    int i = blockIdx.x * blockDim.x + threadIdx.x;   // 0 .. L*64-1
    {   // input: exact 2-term fp16 split
        int row = i >> 6, P = i & 63;
        float v0 = in[row * 128 + 2 * P];
        float v1 = in[row * 128 + 2 * P + 1];
        float h0 = f16hi(v0), h1 = f16hi(v1);
        int col = pair_pos(P);
        g_inH[row * 64 + col] = packh(h0, h1);
        g_inL[row * 64 + col] = packh(v0 - h0, v1 - h1);
    }
    if (i < NSEQ * 64) {   // W1: single-term fp16
        int row = i >> 6, P = i & 63;
        float v0, v1;
        if (row < P_DIM) {
            v0 = B[(row * H_DIM + 2 * P) * 2 + 0];
            v1 = B[(row * H_DIM + 2 * P + 1) * 2 + 0];
        } else {
            int r = row - P_DIM;
            v0 = B[(r * H_DIM + 2 * P) * 2 + 1];
            v1 = B[(r * H_DIM + 2 * P + 1) * 2 + 1];
        }
        int col = pair_pos(P);
        g_W1H[row * 64 + col] = packh(f16hi(v0), f16hi(v1));
    }
    if (i < H_DIM * 256) {  // W2: single-term fp16
        int row = i >> 8, P = i & 255;
        int k0 = 2 * P;
        float v0, v1;
        if (k0 < P_DIM) {
            v0 =  C[(row * P_DIM + k0) * 2 + 0];
            v1 =  C[(row * P_DIM + k0 + 1) * 2 + 0];
        } else {
            v0 = -C[(row * P_DIM + k0 - P_DIM) * 2 + 1];
            v1 = -C[(row * P_DIM + k0 + 1 - P_DIM) * 2 + 1];
        }
        int col = pair_pos(P);
        g_W2H[row * 256 + col] = packh(f16hi(v0), f16hi(v1));
    }
}

// ---------------------------------------------------------------------------
__device__ __forceinline__ void get_consts(const float* __restrict__ A_diag,
                                           const float* __restrict__ steps, int p,
                                           float& m11, float& m12, float& m21, float& m22,
                                           float& c1, float& c2) {
    float A  = fmaxf(A_diag[p], 0.0f);
    float dt = 1.0f / (1.0f + __expf(-steps[p]));
    float schur = 1.0f / (1.0f + dt * dt * A);
    m11 = 1.0f - dt * dt * A * schur;
    m12 = -dt * A * schur;
    m21 = dt * schur;
    m22 = schur;
    c1 = m11 * dt;
    c2 = m21 * dt;
}

// ---------------------------------------------------------------------------
// 2xFP16 NT GEMM (A exact hi+lo, B single-term). BM=64, BN=64, BK=32,
// 128 threads (4 warps 2x2, warp tile 32x32).
// smem/stage (u32): AH 1024 | AL 1024 | BH 1024 = 3072 (12KB); 2 stages 24KB.
#define OFF_AL 1024
#define OFF_BH 2048
#define STAGE_U 3072
#define SBU_STR 65

template <bool FUSE, bool EPI>
__global__ void __launch_bounds__(128)
gemm_f16x2(const uint32_t* __restrict__ AH_g, const uint32_t* __restrict__ AL_g,
           const uint32_t* __restrict__ BH_g,
           float* __restrict__ out, int M, int N, int K,
           const float* __restrict__ resid, const float* __restrict__ Dv,
           const float* __restrict__ A_diag, const float* __restrict__ steps) {
    extern __shared__ uint32_t smem_u[];
    const int tid  = threadIdx.x;
    const int lane = tid & 31;
    const int wid  = tid >> 5;
    const int warp_m = (wid & 1) * 32;
    const int warp_n = (wid >> 1) * 32;
    const int gr = lane >> 2;
    const int kq = lane & 3;
    const int bm = blockIdx.y * 64, bn = blockIdx.x * 64;
    const int KW = K >> 1;

    float acc[2][4][4];
    #pragma unroll
    for (int i = 0; i < 2; i++)
        #pragma unroll
        for (int j = 0; j < 4; j++)
            #pragma unroll
            for (int q = 0; q < 4; q++) acc[i][j][q] = 0.0f;

    const int nk = K >> 5;

    auto stage_load = [&](int kt, int s) {
        uint32_t* base = smem_u + s * STAGE_U;
        int kofs = kt << 4;
        #pragma unroll
        for (int it = 0; it < 2; it++) {
            int id = tid + it * 128;
            int r = id >> 2, c4 = (id & 3) << 2;
            CP16((uint32_t)__cvta_generic_to_shared(base + r * 16 + c4),
                 AH_g + (size_t)(bm + r) * KW + kofs + c4);
            CP16((uint32_t)__cvta_generic_to_shared(base + OFF_AL + r * 16 + c4),
                 AL_g + (size_t)(bm + r) * KW + kofs + c4);
            CP16((uint32_t)__cvta_generic_to_shared(base + OFF_BH + r * 16 + c4),
                 BH_g + (size_t)(bn + r) * KW + kofs + c4);
        }
    };

    stage_load(0, 0);
    asm volatile("cp.async.commit_group;\n");

    for (int kt = 0; kt < nk; kt++) {
        int s = kt & 1;
        if (kt + 1 < nk) stage_load(kt + 1, s ^ 1);
        asm volatile("cp.async.commit_group;\n");
        asm volatile("cp.async.wait_group 1;\n");
        __syncthreads();

        uint32_t* base = smem_u + s * STAGE_U;
        uint4 AH[2][2], AL[2][2];
        #pragma unroll
        for (int mt = 0; mt < 2; mt++) {
            int r0 = warp_m + mt * 16 + gr;
            AH[mt][0] = *reinterpret_cast<uint4*>(base + r0 * 16 + kq * 4);
            AH[mt][1] = *reinterpret_cast<uint4*>(base + (r0 + 8) * 16 + kq * 4);
            AL[mt][0] = *reinterpret_cast<uint4*>(base + OFF_AL + r0 * 16 + kq * 4);
            AL[mt][1] = *reinterpret_cast<uint4*>(base + OFF_AL + (r0 + 8) * 16 + kq * 4);
        }
        #pragma unroll
        for (int nt = 0; nt < 4; nt++) {
            int c0 = warp_n + nt * 8 + gr;
            uint4 BH = *reinterpret_cast<uint4*>(base + OFF_BH + c0 * 16 + kq * 4);
            #pragma unroll
            for (int mt = 0; mt < 2; mt++) {
                float* d = acc[mt][nt];
                // sub-k 0: pairs .x (k=2kq), .y (k=2kq+8)
                mma_f16(d, AH[mt][0].x, AH[mt][1].x, AH[mt][0].y, AH[mt][1].y, BH.x, BH.y);
                mma_f16(d, AL[mt][0].x, AL[mt][1].x, AL[mt][0].y, AL[mt][1].y, BH.x, BH.y);
                // sub-k 1: pairs .z, .w
                mma_f16(d, AH[mt][0].z, AH[mt][1].z, AH[mt][0].w, AH[mt][1].w, BH.z, BH.w);
                mma_f16(d, AL[mt][0].z, AL[mt][1].z, AL[mt][0].w, AL[mt][1].w, BH.z, BH.w);
            }
        }
        __syncthreads();
    }

    // ---------------- Epilogue ----------------
    if (FUSE) {
        // write Bu to gmem + smem (stride 65); fused passA: 64 seqs x 2 chunks.
        float* sbu = reinterpret_cast<float*>(smem_u);
        #pragma unroll
        for (int mt = 0; mt < 2; mt++)
            #pragma unroll
            for (int nt = 0; nt < 4; nt++) {
                int r0 = warp_m + mt * 16 + gr;
                int col = warp_n + nt * 8 + 2 * kq;
                float v00 = acc[mt][nt][0], v01 = acc[mt][nt][1];
                float v10 = acc[mt][nt][2], v11 = acc[mt][nt][3];
                *reinterpret_cast<float2*>(&out[(size_t)(bm + r0) * N + bn + col]) =
                    make_float2(v00, v01);
                *reinterpret_cast<float2*>(&out[(size_t)(bm + r0 + 8) * N + bn + col]) =
                    make_float2(v10, v11);
                sbu[r0 * SBU_STR + col] = v00;       sbu[r0 * SBU_STR + col + 1] = v01;
                sbu[(r0 + 8) * SBU_STR + col] = v10; sbu[(r0 + 8) * SBU_STR + col + 1] = v11;
            }
        __syncthreads();
        {
            int sl = tid & 63;           // local seq
            int cc = tid >> 6;           // sub-chunk 0..1
            int seq = bn + sl;
            int p = seq & (P_DIM - 1);
            float m11, m12, m21, m22, c1, c2;
            get_consts(A_diag, steps, p, m11, m12, m21, m22, c1, c2);
            float x1 = 0.0f, x2 = 0.0f;
            #pragma unroll 8
            for (int s = 0; s < CLEN; s++) {
                float u = sbu[(cc * CLEN + s) * SBU_STR + sl];
                float n1 = fmaf(m11, x1, fmaf(m12, x2, c1 * u));
                float n2 = fmaf(m21, x1, fmaf(m22, x2, c2 * u));
                x1 = n1; x2 = n2;
            }
            g_final[(size_t)seq * NCHUNK + blockIdx.y * 2 + cc] = make_float2(x1, x2);
        }
    } else {
        #pragma unroll
        for (int mt = 0; mt < 2; mt++)
            #pragma unroll
            for (int nt = 0; nt < 4; nt++) {
                int row = bm + warp_m + mt * 16 + gr;
                int col = bn + warp_n + nt * 8 + 2 * kq;
                float2 v0 = make_float2(acc[mt][nt][0], acc[mt][nt][1]);
                float2 v1 = make_float2(acc[mt][nt][2], acc[mt][nt][3]);
                if (EPI) {
                    float2 r0 = *reinterpret_cast<const float2*>(&resid[(size_t)row * N + col]);
                    float2 r1 = *reinterpret_cast<const float2*>(&resid[(size_t)(row + 8) * N + col]);
                    float d0 = Dv[col], d1 = Dv[col + 1];
                    v0.x += r0.x * d0; v0.y += r0.y * d1;
                    v1.x += r1.x * d0; v1.y += r1.y * d1;
                }
                *reinterpret_cast<float2*>(&out[(size_t)row * N + col]) = v0;
                *reinterpret_cast<float2*>(&out[(size_t)(row + 8) * N + col]) = v1;
            }
    }
}

// ---------------------------------------------------------------------------
// Pass B: warp-per-seq shuffle scan over 512 chunk composites (16 per lane).
__global__ void scan_passB_shfl(const float* __restrict__ A_diag,
                                const float* __restrict__ steps) {
    int seq  = blockIdx.x * 8 + (threadIdx.x >> 5);
    int lane = threadIdx.x & 31;
    int p = seq & (P_DIM - 1);
    float m11, m12, m21, m22, c1u, c2u;
    get_consts(A_diag, steps, p, m11, m12, m21, m22, c1u, c2u);

    // P = M^32 (5 squarings)
    float a = m11, b = m12, c = m21, d = m22;
    #pragma unroll
    for (int i = 0; i < 5; i++) {
        float na = a * a + b * c, nb = a * b + b * d;
        float nc = c * a + d * c, nd = c * b + d * d;
        a = na; b = nb; c = nc; d = nd;
    }

    float2 f[16];
    #pragma unroll
    for (int j = 0; j < 16; j++)
        f[j] = g_final[(size_t)seq * NCHUNK + 16 * lane + j];

    float s1 = f[0].x, s2 = f[0].y;
    #pragma unroll
    for (int j = 1; j < 16; j++) {
        float t1 = fmaf(a, s1, fmaf(b, s2, f[j].x));
        float t2 = fmaf(c, s1, fmaf(d, s2, f[j].y));
        s1 = t1; s2 = t2;
    }

    // Q = P^16 (4 squarings)
    float qa = a, qb = b, qc = c, qd = d;
    #pragma unroll
    for (int i = 0; i < 4; i++) {
        float na = qa * qa + qb * qc, nb = qa * qb + qb * qd;
        float nc = qc * qa + qd * qc, nd = qc * qb + qd * qd;
        qa = na; qb = nb; qc = nc; qd = nd;
    }

    #pragma unroll
    for (int dstep = 1; dstep < 32; dstep <<= 1) {
        float u1 = __shfl_up_sync(0xffffffffu, s1, dstep);
        float u2 = __shfl_up_sync(0xffffffffu, s2, dstep);
        if (lane >= dstep) {
            s1 = fmaf(qa, u1, fmaf(qb, u2, s1));
            s2 = fmaf(qc, u1, fmaf(qd, u2, s2));
        }
        float na = qa * qa + qb * qc, nb = qa * qb + qb * qd;
        float nc = qc * qa + qd * qc, nd = qc * qb + qd * qd;
        qa = na; qb = nb; qc = nc; qd = nd;
    }

    float e1 = __shfl_up_sync(0xffffffffu, s1, 1);
    float e2 = __shfl_up_sync(0xffffffffu, s2, 1);
    if (lane == 0) { e1 = 0.0f; e2 = 0.0f; }

    g_initv[(size_t)(16 * lane) * NSEQ + seq] = make_float2(e1, e2);
    #pragma unroll
    for (int j = 1; j < 16; j++) {
        float t1 = fmaf(a, e1, fmaf(b, e2, f[j - 1].x));
        float t2 = fmaf(c, e1, fmaf(d, e2, f[j - 1].y));
        e1 = t1; e2 = t2;
        g_initv[(size_t)(16 * lane + j) * NSEQ + seq] = make_float2(e1, e2);
    }
}

// ---------------------------------------------------------------------------
// Pass C: 2 seqs/thread, 4-deep prefetch ring; fp16 hi/lo u32 pair stores.
__global__ void __launch_bounds__(256)
scan_passC(const float* __restrict__ A_diag, const float* __restrict__ steps) {
    int t = threadIdx.x;               // 0..255 ; seqs 2t, 2t+1
    int c = blockIdx.x;                // chunk 0..511
    int s0 = 2 * t, s1 = 2 * t + 1;
    float a11, a12, a21, a22, ac1, ac2;
    float b11, b12, b21, b22, bc1, bc2;
    get_consts(A_diag, steps, s0 & (P_DIM - 1), a11, a12, a21, a22, ac1, ac2);
    get_consts(A_diag, steps, s1 & (P_DIM - 1), b11, b12, b21, b22, bc1, bc2);

    float2 i0 = g_initv[(size_t)c * NSEQ + s0];
    float2 i1 = g_initv[(size_t)c * NSEQ + s1];
    float x1a = i0.x, x2a = i0.y, x1b = i1.x, x2b = i1.y;

    int col = pair_pos(t);
    const float* bu = g_buall + (size_t)c * CLEN * NSEQ + s0;
    uint32_t* xh = g_x2H + (size_t)c * CLEN * 256 + col;
    uint32_t* xl = g_x2L + (size_t)c * CLEN * 256 + col;

    float2 ubuf[4];
    #pragma unroll
    for (int j = 0; j < 4; j++)
        ubuf[j] = *reinterpret_cast<const float2*>(bu + (size_t)j * NSEQ);

    #pragma unroll
    for (int s = 0; s < CLEN; s++) {
        float2 u = ubuf[s & 3];
        if (s + 4 < CLEN)
            ubuf[s & 3] = *reinterpret_cast<const float2*>(bu + (size_t)(s + 4) * NSEQ);
        float n1a = fmaf(a11, x1a, fmaf(a12, x2a, ac1 * u.x));
        float n2a = fmaf(a21, x1a, fmaf(a22, x2a, ac2 * u.x));
        float n1b = fmaf(b11, x1b, fmaf(b12, x2b, bc1 * u.y));
        float n2b = fmaf(b21, x1b, fmaf(b22, x2b, bc2 * u.y));
        x1a = n1a; x2a = n2a; x1b = n1b; x2b = n2b;
        float h0 = f16hi(x2a), h1 = f16hi(x2b);
        xh[(size_t)s * 256] = packh(h0, h1);
        xl[(size_t)s * 256] = packh(x2a - h0, x2b - h1);
    }
}

// ---------------------------------------------------------------------------
extern "C" void kernel_launch(void* const* d_in, const int* in_sizes, int n_in,
                              void* d_out, int out_size) {
    const float* input  = (const float*)d_in[0];  // (L, H)
    const float* A_diag = (const float*)d_in[1];  // (P,)
    const float* B      = (const float*)d_in[2];  // (P, H, 2)
    const float* C      = (const float*)d_in[3];  // (H, P, 2)
    const float* D      = (const float*)d_in[4];  // (H,)
    const float* steps  = (const float*)d_in[5];  // (P,)
    float* out = (float*)d_out;                   // (L, H)

    float *p_bu;
    uint32_t *p_inH, *p_inL, *p_w1H, *p_w2H, *p_x2H, *p_x2L;
    cudaGetSymbolAddress((void**)&p_bu,  g_buall);
    cudaGetSymbolAddress((void**)&p_inH, g_inH);
    cudaGetSymbolAddress((void**)&p_inL, g_inL);
    cudaGetSymbolAddress((void**)&p_w1H, g_W1H);
    cudaGetSymbolAddress((void**)&p_w2H, g_W2H);
    cudaGetSymbolAddress((void**)&p_x2H, g_x2H);
    cudaGetSymbolAddress((void**)&p_x2L, g_x2L);

    const int dyn = STAGE_U * 2 * sizeof(uint32_t);   // 24576 bytes (>= 64*65*4)
    cudaFuncSetAttribute(gemm_f16x2<true, false>,
                         cudaFuncAttributeMaxDynamicSharedMemorySize, dyn);
    cudaFuncSetAttribute(gemm_f16x2<false, true>,
                         cudaFuncAttributeMaxDynamicSharedMemorySize, dyn);

    prep_all<<<L_SEQ * 64 / 256, 256>>>(input, B, C);

    // GEMM1 + fused passA: Bu = input @ W1^T  (16384 x 512, K=128)
    gemm_f16x2<true, false><<<dim3(NSEQ / 64, L_SEQ / 64), 128, dyn>>>(
        p_inH, p_inL, p_w1H, p_bu, L_SEQ, NSEQ, H_DIM,
        nullptr, nullptr, A_diag, steps);

    scan_passB_shfl<<<NSEQ / 8, 256>>>(A_diag, steps);
    scan_passC<<<NCHUNK, 256>>>(A_diag, steps);

    // GEMM2: ys = x2 @ W2^T + input * D  (16384 x 128, K=512)
    gemm_f16x2<false, true><<<dim3(H_DIM / 64, L_SEQ / 64), 128, dyn>>>(
        p_x2H, p_x2L, p_w2H, out, L_SEQ, H_DIM, NSEQ,
        input, D, nullptr, nullptr);
}

// round 17
// speedup vs baseline: 1.5064x; 1.1429x over previous
#include <cuda_runtime.h>
#include <cuda_fp16.h>
#include <math.h>
#include <stdint.h>

#define L_SEQ 16384
#define H_DIM 128
#define P_DIM 256
#define NSEQ  512          // 256 channels x {re, im}
#define NCHUNK 512
#define CLEN   32          // NCHUNK * CLEN == L_SEQ

// ---------------------------------------------------------------------------
// Scratch (device globals)
__device__ float    g_buall[L_SEQ * NSEQ];        // fp32 Bu (for passC)
__device__ uint32_t g_inH[L_SEQ * (H_DIM / 2)];   // input hi fp16-pairs, permuted
__device__ uint32_t g_inL[L_SEQ * (H_DIM / 2)];   // input lo fp16-pairs
__device__ uint32_t g_W1H[NSEQ * (H_DIM / 2)];    // [Br;Bi] fp16 (single term)
__device__ uint32_t g_W2H[H_DIM * (NSEQ / 2)];    // [Cr,-Ci] fp16 (single term)
__device__ uint32_t g_x2H[L_SEQ * (NSEQ / 2)];    // x2 fp16 (single term), permuted
__device__ float2   g_final[NSEQ * NCHUNK];       // [seq][chunk]
__device__ float2   g_initv[NCHUNK * NSEQ];       // [chunk][seq]

// ---------------------------------------------------------------------------
__device__ __forceinline__ uint32_t packh(float lo, float hi) {  // lo -> bits[15:0]
    uint32_t r;
    asm("cvt.rn.f16x2.f32 %0, %1, %2;" : "=r"(r) : "f"(hi), "f"(lo));
    return r;
}
__device__ __forceinline__ int pair_pos(int P) {  // permute pairs within 16-pair groups
    int pi = P & 15;
    return (P & ~15) | (((pi & 3) << 2) | (pi >> 2));
}
__device__ __forceinline__ float f16hi(float v) {
    return __half2float(__float2half_rn(v));
}
__device__ __forceinline__ void mma_f16(float* d, uint32_t a0, uint32_t a1,
                                        uint32_t a2, uint32_t a3,
                                        uint32_t b0, uint32_t b1) {
    asm volatile(
        "mma.sync.aligned.m16n8k16.row.col.f32.f16.f16.f32 "
        "{%0,%1,%2,%3},{%4,%5,%6,%7},{%8,%9},{%0,%1,%2,%3};\n"
        : "+f"(d[0]), "+f"(d[1]), "+f"(d[2]), "+f"(d[3])
        : "r"(a0), "r"(a1), "r"(a2), "r"(a3), "r"(b0), "r"(b1));
}
#define CP16(dst_u32, src_ptr) \
    asm volatile("cp.async.cg.shared.global [%0], [%1], 16;\n" :: "r"(dst_u32), "l"(src_ptr))

// ---------------------------------------------------------------------------
// Merged prep: input split (hi+lo) + W1/W2 single-term fp16 packs.
__global__ void prep_all(const float* __restrict__ in, const float* __restrict__ B,
                         const float* __restrict__ C) {
    int i = blockIdx.x * blockDim.x + threadIdx.x;   // 0 .. L*64-1
    {   // input: exact 2-term fp16 split
        int row = i >> 6, P = i & 63;
        float v0 = in[row * 128 + 2 * P];
        float v1 = in[row * 128 + 2 * P + 1];
        float h0 = f16hi(v0), h1 = f16hi(v1);
        int col = pair_pos(P);
        g_inH[row * 64 + col] = packh(h0, h1);
        g_inL[row * 64 + col] = packh(v0 - h0, v1 - h1);
    }
    if (i < NSEQ * 64) {   // W1: single-term fp16
        int row = i >> 6, P = i & 63;
        float v0, v1;
        if (row < P_DIM) {
            v0 = B[(row * H_DIM + 2 * P) * 2 + 0];
            v1 = B[(row * H_DIM + 2 * P + 1) * 2 + 0];
        } else {
            int r = row - P_DIM;
            v0 = B[(r * H_DIM + 2 * P) * 2 + 1];
            v1 = B[(r * H_DIM + 2 * P + 1) * 2 + 1];
        }
        int col = pair_pos(P);
        g_W1H[row * 64 + col] = packh(f16hi(v0), f16hi(v1));
    }
    if (i < H_DIM * 256) {  // W2: single-term fp16
        int row = i >> 8, P = i & 255;
        int k0 = 2 * P;
        float v0, v1;
        if (k0 < P_DIM) {
            v0 =  C[(row * P_DIM + k0) * 2 + 0];
            v1 =  C[(row * P_DIM + k0 + 1) * 2 + 0];
        } else {
            v0 = -C[(row * P_DIM + k0 - P_DIM) * 2 + 1];
            v1 = -C[(row * P_DIM + k0 + 1 - P_DIM) * 2 + 1];
        }
        int col = pair_pos(P);
        g_W2H[row * 256 + col] = packh(f16hi(v0), f16hi(v1));
    }
}

// ---------------------------------------------------------------------------
__device__ __forceinline__ void get_consts(const float* __restrict__ A_diag,
                                           const float* __restrict__ steps, int p,
                                           float& m11, float& m12, float& m21, float& m22,
                                           float& c1, float& c2) {
    float A  = fmaxf(A_diag[p], 0.0f);
    float dt = 1.0f / (1.0f + __expf(-steps[p]));
    float schur = 1.0f / (1.0f + dt * dt * A);
    m11 = 1.0f - dt * dt * A * schur;
    m12 = -dt * A * schur;
    m21 = dt * schur;
    m22 = schur;
    c1 = m11 * dt;
    c2 = m21 * dt;
}

// ---------------------------------------------------------------------------
// FP16 NT GEMM. ALO: A has exact hi+lo split (2 MMAs); else single-term (1 MMA).
// BM=64, BN=64, BK=32, 128 threads (4 warps 2x2, warp tile 32x32).
// smem/stage (u32): AH 1024 | [AL 1024] | BH 1024.
#define SBU_STR 65

template <bool FUSE, bool EPI, bool ALO>
__global__ void __launch_bounds__(128)
gemm_f16(const uint32_t* __restrict__ AH_g, const uint32_t* __restrict__ AL_g,
         const uint32_t* __restrict__ BH_g,
         float* __restrict__ out, int M, int N, int K,
         const float* __restrict__ resid, const float* __restrict__ Dv,
         const float* __restrict__ A_diag, const float* __restrict__ steps) {
    extern __shared__ uint32_t smem_u[];
    const int STAGE = ALO ? 3072 : 2048;
    const int OFF_AL = 1024;                 // only used when ALO
    const int OFF_BH = ALO ? 2048 : 1024;
    const int tid  = threadIdx.x;
    const int lane = tid & 31;
    const int wid  = tid >> 5;
    const int warp_m = (wid & 1) * 32;
    const int warp_n = (wid >> 1) * 32;
    const int gr = lane >> 2;
    const int kq = lane & 3;
    const int bm = blockIdx.y * 64, bn = blockIdx.x * 64;
    const int KW = K >> 1;

    float acc[2][4][4];
    #pragma unroll
    for (int i = 0; i < 2; i++)
        #pragma unroll
        for (int j = 0; j < 4; j++)
            #pragma unroll
            for (int q = 0; q < 4; q++) acc[i][j][q] = 0.0f;

    const int nk = K >> 5;

    auto stage_load = [&](int kt, int s) {
        uint32_t* base = smem_u + s * STAGE;
        int kofs = kt << 4;
        #pragma unroll
        for (int it = 0; it < 2; it++) {
            int id = tid + it * 128;
            int r = id >> 2, c4 = (id & 3) << 2;
            CP16((uint32_t)__cvta_generic_to_shared(base + r * 16 + c4),
                 AH_g + (size_t)(bm + r) * KW + kofs + c4);
            if (ALO)
                CP16((uint32_t)__cvta_generic_to_shared(base + OFF_AL + r * 16 + c4),
                     AL_g + (size_t)(bm + r) * KW + kofs + c4);
            CP16((uint32_t)__cvta_generic_to_shared(base + OFF_BH + r * 16 + c4),
                 BH_g + (size_t)(bn + r) * KW + kofs + c4);
        }
    };

    stage_load(0, 0);
    asm volatile("cp.async.commit_group;\n");

    for (int kt = 0; kt < nk; kt++) {
        int s = kt & 1;
        if (kt + 1 < nk) stage_load(kt + 1, s ^ 1);
        asm volatile("cp.async.commit_group;\n");
        asm volatile("cp.async.wait_group 1;\n");
        __syncthreads();

        uint32_t* base = smem_u + s * STAGE;
        uint4 AH[2][2], AL[2][2];
        #pragma unroll
        for (int mt = 0; mt < 2; mt++) {
            int r0 = warp_m + mt * 16 + gr;
            AH[mt][0] = *reinterpret_cast<uint4*>(base + r0 * 16 + kq * 4);
            AH[mt][1] = *reinterpret_cast<uint4*>(base + (r0 + 8) * 16 + kq * 4);
            if (ALO) {
                AL[mt][0] = *reinterpret_cast<uint4*>(base + OFF_AL + r0 * 16 + kq * 4);
                AL[mt][1] = *reinterpret_cast<uint4*>(base + OFF_AL + (r0 + 8) * 16 + kq * 4);
            }
        }
        #pragma unroll
        for (int nt = 0; nt < 4; nt++) {
            int c0 = warp_n + nt * 8 + gr;
            uint4 BH = *reinterpret_cast<uint4*>(base + OFF_BH + c0 * 16 + kq * 4);
            #pragma unroll
            for (int mt = 0; mt < 2; mt++) {
                float* d = acc[mt][nt];
                mma_f16(d, AH[mt][0].x, AH[mt][1].x, AH[mt][0].y, AH[mt][1].y, BH.x, BH.y);
                if (ALO)
                    mma_f16(d, AL[mt][0].x, AL[mt][1].x, AL[mt][0].y, AL[mt][1].y, BH.x, BH.y);
                mma_f16(d, AH[mt][0].z, AH[mt][1].z, AH[mt][0].w, AH[mt][1].w, BH.z, BH.w);
                if (ALO)
                    mma_f16(d, AL[mt][0].z, AL[mt][1].z, AL[mt][0].w, AL[mt][1].w, BH.z, BH.w);
            }
        }
        __syncthreads();
    }

    // ---------------- Epilogue ----------------
    if (FUSE) {
        // write Bu to gmem + smem (stride 65); fused passA: 64 seqs x 2 chunks.
        float* sbu = reinterpret_cast<float*>(smem_u);
        #pragma unroll
        for (int mt = 0; mt < 2; mt++)
            #pragma unroll
            for (int nt = 0; nt < 4; nt++) {
                int r0 = warp_m + mt * 16 + gr;
                int col = warp_n + nt * 8 + 2 * kq;
                float v00 = acc[mt][nt][0], v01 = acc[mt][nt][1];
                float v10 = acc[mt][nt][2], v11 = acc[mt][nt][3];
                *reinterpret_cast<float2*>(&out[(size_t)(bm + r0) * N + bn + col]) =
                    make_float2(v00, v01);
                *reinterpret_cast<float2*>(&out[(size_t)(bm + r0 + 8) * N + bn + col]) =
                    make_float2(v10, v11);
                sbu[r0 * SBU_STR + col] = v00;       sbu[r0 * SBU_STR + col + 1] = v01;
                sbu[(r0 + 8) * SBU_STR + col] = v10; sbu[(r0 + 8) * SBU_STR + col + 1] = v11;
            }
        __syncthreads();
        {
            int sl = tid & 63;           // local seq
            int cc = tid >> 6;           // sub-chunk 0..1
            int seq = bn + sl;
            int p = seq & (P_DIM - 1);
            float m11, m12, m21, m22, c1, c2;
            get_consts(A_diag, steps, p, m11, m12, m21, m22, c1, c2);
            float x1 = 0.0f, x2 = 0.0f;
            #pragma unroll 8
            for (int s = 0; s < CLEN; s++) {
                float u = sbu[(cc * CLEN + s) * SBU_STR + sl];
                float n1 = fmaf(m11, x1, fmaf(m12, x2, c1 * u));
                float n2 = fmaf(m21, x1, fmaf(m22, x2, c2 * u));
                x1 = n1; x2 = n2;
            }
            g_final[(size_t)seq * NCHUNK + blockIdx.y * 2 + cc] = make_float2(x1, x2);
        }
    } else {
        #pragma unroll
        for (int mt = 0; mt < 2; mt++)
            #pragma unroll
            for (int nt = 0; nt < 4; nt++) {
                int row = bm + warp_m + mt * 16 + gr;
                int col = bn + warp_n + nt * 8 + 2 * kq;
                float2 v0 = make_float2(acc[mt][nt][0], acc[mt][nt][1]);
                float2 v1 = make_float2(acc[mt][nt][2], acc[mt][nt][3]);
                if (EPI) {
                    float2 r0 = *reinterpret_cast<const float2*>(&resid[(size_t)row * N + col]);
                    float2 r1 = *reinterpret_cast<const float2*>(&resid[(size_t)(row + 8) * N + col]);
                    float d0 = Dv[col], d1 = Dv[col + 1];
                    v0.x += r0.x * d0; v0.y += r0.y * d1;
                    v1.x += r1.x * d0; v1.y += r1.y * d1;
                }
                *reinterpret_cast<float2*>(&out[(size_t)row * N + col]) = v0;
                *reinterpret_cast<float2*>(&out[(size_t)(row + 8) * N + col]) = v1;
            }
    }
}

// ---------------------------------------------------------------------------
// Pass B: warp-per-seq shuffle scan over 512 chunk composites (16 per lane).
__global__ void scan_passB_shfl(const float* __restrict__ A_diag,
                                const float* __restrict__ steps) {
    int seq  = blockIdx.x * 8 + (threadIdx.x >> 5);
    int lane = threadIdx.x & 31;
    int p = seq & (P_DIM - 1);
    float m11, m12, m21, m22, c1u, c2u;
    get_consts(A_diag, steps, p, m11, m12, m21, m22, c1u, c2u);

    // P = M^32 (5 squarings)
    float a = m11, b = m12, c = m21, d = m22;
    #pragma unroll
    for (int i = 0; i < 5; i++) {
        float na = a * a + b * c, nb = a * b + b * d;
        float nc = c * a + d * c, nd = c * b + d * d;
        a = na; b = nb; c = nc; d = nd;
    }

    float2 f[16];
    #pragma unroll
    for (int j = 0; j < 16; j++)
        f[j] = g_final[(size_t)seq * NCHUNK + 16 * lane + j];

    float s1 = f[0].x, s2 = f[0].y;
    #pragma unroll
    for (int j = 1; j < 16; j++) {
        float t1 = fmaf(a, s1, fmaf(b, s2, f[j].x));
        float t2 = fmaf(c, s1, fmaf(d, s2, f[j].y));
        s1 = t1; s2 = t2;
    }

    // Q = P^16 (4 squarings)
    float qa = a, qb = b, qc = c, qd = d;
    #pragma unroll
    for (int i = 0; i < 4; i++) {
        float na = qa * qa + qb * qc, nb = qa * qb + qb * qd;
        float nc = qc * qa + qd * qc, nd = qc * qb + qd * qd;
        qa = na; qb = nb; qc = nc; qd = nd;
    }

    #pragma unroll
    for (int dstep = 1; dstep < 32; dstep <<= 1) {
        float u1 = __shfl_up_sync(0xffffffffu, s1, dstep);
        float u2 = __shfl_up_sync(0xffffffffu, s2, dstep);
        if (lane >= dstep) {
            s1 = fmaf(qa, u1, fmaf(qb, u2, s1));
            s2 = fmaf(qc, u1, fmaf(qd, u2, s2));
        }
        float na = qa * qa + qb * qc, nb = qa * qb + qb * qd;
        float nc = qc * qa + qd * qc, nd = qc * qb + qd * qd;
        qa = na; qb = nb; qc = nc; qd = nd;
    }

    float e1 = __shfl_up_sync(0xffffffffu, s1, 1);
    float e2 = __shfl_up_sync(0xffffffffu, s2, 1);
    if (lane == 0) { e1 = 0.0f; e2 = 0.0f; }

    g_initv[(size_t)(16 * lane) * NSEQ + seq] = make_float2(e1, e2);
    #pragma unroll
    for (int j = 1; j < 16; j++) {
        float t1 = fmaf(a, e1, fmaf(b, e2, f[j - 1].x));
        float t2 = fmaf(c, e1, fmaf(d, e2, f[j - 1].y));
        e1 = t1; e2 = t2;
        g_initv[(size_t)(16 * lane + j) * NSEQ + seq] = make_float2(e1, e2);
    }
}

// ---------------------------------------------------------------------------
// Pass C: 2 seqs/thread, 4-deep prefetch ring; single fp16 u32 pair store.
__global__ void __launch_bounds__(256)
scan_passC(const float* __restrict__ A_diag, const float* __restrict__ steps) {
    int t = threadIdx.x;               // 0..255 ; seqs 2t, 2t+1
    int c = blockIdx.x;                // chunk 0..511
    int s0 = 2 * t, s1 = 2 * t + 1;
    float a11, a12, a21, a22, ac1, ac2;
    float b11, b12, b21, b22, bc1, bc2;
    get_consts(A_diag, steps, s0 & (P_DIM - 1), a11, a12, a21, a22, ac1, ac2);
    get_consts(A_diag, steps, s1 & (P_DIM - 1), b11, b12, b21, b22, bc1, bc2);

    float2 i0 = g_initv[(size_t)c * NSEQ + s0];
    float2 i1 = g_initv[(size_t)c * NSEQ + s1];
    float x1a = i0.x, x2a = i0.y, x1b = i1.x, x2b = i1.y;

    int col = pair_pos(t);
    const float* bu = g_buall + (size_t)c * CLEN * NSEQ + s0;
    uint32_t* xh = g_x2H + (size_t)c * CLEN * 256 + col;

    float2 ubuf[4];
    #pragma unroll
    for (int j = 0; j < 4; j++)
        ubuf[j] = *reinterpret_cast<const float2*>(bu + (size_t)j * NSEQ);

    #pragma unroll
    for (int s = 0; s < CLEN; s++) {
        float2 u = ubuf[s & 3];
        if (s + 4 < CLEN)
            ubuf[s & 3] = *reinterpret_cast<const float2*>(bu + (size_t)(s + 4) * NSEQ);
        float n1a = fmaf(a11, x1a, fmaf(a12, x2a, ac1 * u.x));
        float n2a = fmaf(a21, x1a, fmaf(a22, x2a, ac2 * u.x));
        float n1b = fmaf(b11, x1b, fmaf(b12, x2b, bc1 * u.y));
        float n2b = fmaf(b21, x1b, fmaf(b22, x2b, bc2 * u.y));
        x1a = n1a; x2a = n2a; x1b = n1b; x2b = n2b;
        xh[(size_t)s * 256] = packh(x2a, x2b);
    }
}

// ---------------------------------------------------------------------------
extern "C" void kernel_launch(void* const* d_in, const int* in_sizes, int n_in,
                              void* d_out, int out_size) {
    const float* input  = (const float*)d_in[0];  // (L, H)
    const float* A_diag = (const float*)d_in[1];  // (P,)
    const float* B      = (const float*)d_in[2];  // (P, H, 2)
    const float* C      = (const float*)d_in[3];  // (H, P, 2)
    const float* D      = (const float*)d_in[4];  // (H,)
    const float* steps  = (const float*)d_in[5];  // (P,)
    float* out = (float*)d_out;                   // (L, H)

    float *p_bu;
    uint32_t *p_inH, *p_inL, *p_w1H, *p_w2H, *p_x2H;
    cudaGetSymbolAddress((void**)&p_bu,  g_buall);
    cudaGetSymbolAddress((void**)&p_inH, g_inH);
    cudaGetSymbolAddress((void**)&p_inL, g_inL);
    cudaGetSymbolAddress((void**)&p_w1H, g_W1H);
    cudaGetSymbolAddress((void**)&p_w2H, g_W2H);
    cudaGetSymbolAddress((void**)&p_x2H, g_x2H);

    const int dyn1 = 3072 * 2 * sizeof(uint32_t);   // 24576 (>= 64*65*4=16640)
    const int dyn2 = 2048 * 2 * sizeof(uint32_t);   // 16384
    cudaFuncSetAttribute(gemm_f16<true, false, true>,
                         cudaFuncAttributeMaxDynamicSharedMemorySize, dyn1);
    cudaFuncSetAttribute(gemm_f16<false, true, false>,
                         cudaFuncAttributeMaxDynamicSharedMemorySize, dyn2);

    prep_all<<<L_SEQ * 64 / 256, 256>>>(input, B, C);

    // GEMM1 (A exact hi+lo) + fused passA: Bu = input @ W1^T
    gemm_f16<true, false, true><<<dim3(NSEQ / 64, L_SEQ / 64), 128, dyn1>>>(
        p_inH, p_inL, p_w1H, p_bu, L_SEQ, NSEQ, H_DIM,
        nullptr, nullptr, A_diag, steps);

    scan_passB_shfl<<<NSEQ / 8, 256>>>(A_diag, steps);
    scan_passC<<<NCHUNK, 256>>>(A_diag, steps);

    // GEMM2 (pure fp16): ys = x2 @ W2^T + input * D
    gemm_f16<false, true, false><<<dim3(H_DIM / 64, L_SEQ / 64), 128, dyn2>>>(
        p_x2H, nullptr, p_w2H, out, L_SEQ, H_DIM, NSEQ,
        input, D, nullptr, nullptr);
}